// round 4
// baseline (speedup 1.0000x reference)
#include <cuda_runtime.h>
#include <cuda_bf16.h>

// Problem shape (fixed): q,k,v fp32 [B, S, H, D], out fp32 [B, S, H, D]
#define Bz 2
#define Sq 4096
#define Hh 8
#define Dd 64
#define HD (Hh * Dd) // 512 floats row stride over (h,d)

// Tiling
#define BM 128 // q rows per CTA
#define BN 64  // kv rows per tile
#define NT 128 // threads per CTA

// Padded smem row strides (floats)
#define QS 132 // Qs[d][row], row-padded
#define KS 68  // Ks[d][col]
#define VS 72  // Vs[k][d] (multiple of 4 for float4 stores)
#define PS 132 // Ps[col][row]

#define SMEM_FLOATS (64 * QS + 64 * KS + 64 * VS + 64 * PS)
#define SMEM_BYTES (SMEM_FLOATS * 4)

__global__ __launch_bounds__(NT)
void SimpleRingAttention_76312978915795_kernel(
    const float* __restrict__ q, const float* __restrict__ k,
    const float* __restrict__ v, float* __restrict__ out)
{
    extern __shared__ float sm[];
    float* Qs  = sm;                  // [64][QS]  transposed, pre-scaled
    float* Ksm = Qs  + 64 * QS;       // [64][KS]  transposed
    float* Vsm = Ksm + 64 * KS;       // [64][VS]  row-major
    float* Psm = Vsm + 64 * VS;       // [64][PS]  transposed (col-major P)

    const int tid = threadIdx.x;
    const int m0  = blockIdx.x * BM;
    const int h   = blockIdx.y;
    const int b   = blockIdx.z;

    const int rb = tid >> 3;   // 0..15 row block
    const int cb = tid & 7;    // 0..7  col block
    const int r0 = rb * 8;
    const int c0 = cb * 8;

    const float scale = 0.125f; // 1/sqrt(64)
    const float* qbase = q + ((size_t)b * Sq + m0) * HD + h * Dd;
    const float* kbase = k + ((size_t)b * Sq) * HD + h * Dd;
    const float* vbase = v + ((size_t)b * Sq) * HD + h * Dd;

    // ---- Load Q tile [BM][64] -> Qs[d][row], scaled ----
    #pragma unroll
    for (int i = 0; i < 16; i++) {
        int idx = tid + i * NT;       // 0..2047 float4 slots
        int row = idx >> 4;           // 0..127
        int d4  = (idx & 15) << 2;    // 0,4,...,60
        float4 t = *reinterpret_cast<const float4*>(qbase + (size_t)row * HD + d4);
        Qs[(d4 + 0) * QS + row] = t.x * scale;
        Qs[(d4 + 1) * QS + row] = t.y * scale;
        Qs[(d4 + 2) * QS + row] = t.z * scale;
        Qs[(d4 + 3) * QS + row] = t.w * scale;
    }

    float m_i[8], l_i[8];
    float oacc[8][8];
    #pragma unroll
    for (int i = 0; i < 8; i++) {
        m_i[i] = -1e30f;
        l_i[i] = 0.0f;
        #pragma unroll
        for (int j = 0; j < 8; j++) oacc[i][j] = 0.0f;
    }

    for (int n0 = 0; n0 < Sq; n0 += BN) {
        // Ensure previous iteration's GEMM2 reads of Vsm/Psm are done.
        __syncthreads();

        // ---- Load K tile -> Ksm[d][col] and V tile -> Vsm[k][d] ----
        #pragma unroll
        for (int i = 0; i < 8; i++) {
            int idx = tid + i * NT;    // 0..1023 float4 slots
            int row = idx >> 4;        // 0..63 kv row
            int d4  = (idx & 15) << 2;
            float4 tk = *reinterpret_cast<const float4*>(kbase + (size_t)(n0 + row) * HD + d4);
            Ksm[(d4 + 0) * KS + row] = tk.x;
            Ksm[(d4 + 1) * KS + row] = tk.y;
            Ksm[(d4 + 2) * KS + row] = tk.z;
            Ksm[(d4 + 3) * KS + row] = tk.w;
            float4 tv = *reinterpret_cast<const float4*>(vbase + (size_t)(n0 + row) * HD + d4);
            *reinterpret_cast<float4*>(&Vsm[row * VS + d4]) = tv;
        }
        __syncthreads();

        // ---- GEMM1: S = Qs^T * Ks  (8x8 per thread) ----
        float sacc[8][8];
        #pragma unroll
        for (int i = 0; i < 8; i++)
            #pragma unroll
            for (int j = 0; j < 8; j++) sacc[i][j] = 0.0f;

        #pragma unroll 8
        for (int d = 0; d < Dd; d++) {
            const float* qr = &Qs[d * QS + r0];
            const float* kr = &Ksm[d * KS + c0];
            float4 qa = *reinterpret_cast<const float4*>(qr);
            float4 qb = *reinterpret_cast<const float4*>(qr + 4);
            float4 ka = *reinterpret_cast<const float4*>(kr);
            float4 kb = *reinterpret_cast<const float4*>(kr + 4);
            float qf[8] = {qa.x, qa.y, qa.z, qa.w, qb.x, qb.y, qb.z, qb.w};
            float kf[8] = {ka.x, ka.y, ka.z, ka.w, kb.x, kb.y, kb.z, kb.w};
            #pragma unroll
            for (int i = 0; i < 8; i++)
                #pragma unroll
                for (int j = 0; j < 8; j++)
                    sacc[i][j] += qf[i] * kf[j];
        }

        // ---- Online softmax over this tile ----
        #pragma unroll
        for (int i = 0; i < 8; i++) {
            float mt = sacc[i][0];
            #pragma unroll
            for (int j = 1; j < 8; j++) mt = fmaxf(mt, sacc[i][j]);
            // reduce across the 8 lanes sharing this row (low 3 bits of lane)
            mt = fmaxf(mt, __shfl_xor_sync(0xffffffffu, mt, 1));
            mt = fmaxf(mt, __shfl_xor_sync(0xffffffffu, mt, 2));
            mt = fmaxf(mt, __shfl_xor_sync(0xffffffffu, mt, 4));

            float mnew = fmaxf(m_i[i], mt);
            float corr = __expf(m_i[i] - mnew);
            m_i[i] = mnew;

            float sum = 0.0f;
            #pragma unroll
            for (int j = 0; j < 8; j++) {
                float p = __expf(sacc[i][j] - mnew);
                sacc[i][j] = p;
                sum += p;
            }
            sum += __shfl_xor_sync(0xffffffffu, sum, 1);
            sum += __shfl_xor_sync(0xffffffffu, sum, 2);
            sum += __shfl_xor_sync(0xffffffffu, sum, 4);

            l_i[i] = l_i[i] * corr + sum;
            #pragma unroll
            for (int j = 0; j < 8; j++) oacc[i][j] *= corr;
        }

        // ---- Write P (transposed) to smem ----
        #pragma unroll
        for (int j = 0; j < 8; j++) {
            float* pr = &Psm[(c0 + j) * PS + r0];
            float4 pa = make_float4(sacc[0][j], sacc[1][j], sacc[2][j], sacc[3][j]);
            float4 pb = make_float4(sacc[4][j], sacc[5][j], sacc[6][j], sacc[7][j]);
            *reinterpret_cast<float4*>(pr)     = pa;
            *reinterpret_cast<float4*>(pr + 4) = pb;
        }
        __syncthreads();

        // ---- GEMM2: O += P * V  (8 rows x 8 d-cols per thread) ----
        #pragma unroll 8
        for (int kk = 0; kk < BN; kk++) {
            const float* pr = &Psm[kk * PS + r0];
            const float* vr = &Vsm[kk * VS + c0];
            float4 pa = *reinterpret_cast<const float4*>(pr);
            float4 pb = *reinterpret_cast<const float4*>(pr + 4);
            float4 va = *reinterpret_cast<const float4*>(vr);
            float4 vb = *reinterpret_cast<const float4*>(vr + 4);
            float pf[8] = {pa.x, pa.y, pa.z, pa.w, pb.x, pb.y, pb.z, pb.w};
            float vf[8] = {va.x, va.y, va.z, va.w, vb.x, vb.y, vb.z, vb.w};
            #pragma unroll
            for (int i = 0; i < 8; i++)
                #pragma unroll
                for (int j = 0; j < 8; j++)
                    oacc[i][j] += pf[i] * vf[j];
        }
    }

    // ---- Epilogue: normalize and store ----
    float* obase = out + ((size_t)b * Sq + m0) * HD + h * Dd;
    #pragma unroll
    for (int i = 0; i < 8; i++) {
        float inv = 1.0f / l_i[i];
        float* orow = obase + (size_t)(r0 + i) * HD + c0;
        float4 oa = make_float4(oacc[i][0] * inv, oacc[i][1] * inv,
                                oacc[i][2] * inv, oacc[i][3] * inv);
        float4 ob = make_float4(oacc[i][4] * inv, oacc[i][5] * inv,
                                oacc[i][6] * inv, oacc[i][7] * inv);
        *reinterpret_cast<float4*>(orow)     = oa;
        *reinterpret_cast<float4*>(orow + 4) = ob;
    }
}

extern "C" void kernel_launch(void* const* d_in, const int* in_sizes, int n_in,
                              void* d_out, int out_size)
{
    (void)in_sizes; (void)n_in; (void)out_size;
    const float* q = (const float*)d_in[0];
    const float* k = (const float*)d_in[1];
    const float* v = (const float*)d_in[2];
    float* out = (float*)d_out;

    cudaFuncSetAttribute(SimpleRingAttention_76312978915795_kernel,
                         cudaFuncAttributeMaxDynamicSharedMemorySize, SMEM_BYTES);

    dim3 grid(Sq / BM, Hh, Bz); // 32 x 8 x 2 = 512 CTAs
    SimpleRingAttention_76312978915795_kernel<<<grid, NT, SMEM_BYTES>>>(q, k, v, out);
}

// round 5
// speedup vs baseline: 3.9177x; 3.9177x over previous
#include <cuda_runtime.h>
#include <cuda_bf16.h>
#include <cstdint>

// Shape (fixed): q,k,v fp32 [B=2, S=4096, H=8, D=64], out fp32 same.
#define Bz 2
#define Sq 4096
#define Hh 8
#define Dd 64
#define HD (Hh * Dd)

#define BM 128   // q rows per CTA
#define BN 64    // kv rows per tile
#define NT 256   // 8 warps, 16 q-rows each

// smem strides (floats)
#define QP 72    // Qs[row][d] pad
#define KP 72    // Kt[d][kv] pad (72%32==8 -> conflict-free frag loads)
#define VP 72    // Vs[kv][d] pad
#define PP 68    // per-warp Ps[16][68] (68%32==4 -> conflict-free A-frag loads)

#define QS_FLOATS (BM * QP)           // 9216
#define KT_FLOATS (BN * KP)           // 4608
#define VS_FLOATS (BN * VP)           // 4608
#define PS_FLOATS (8 * 16 * PP)       // 8704
#define SMEM_FLOATS (QS_FLOATS + KT_FLOATS + VS_FLOATS + PS_FLOATS)
#define SMEM_BYTES (SMEM_FLOATS * 4)  // 108,544 B -> 2 CTAs/SM

__device__ __forceinline__ float tf32r(float x) {
    uint32_t u;
    asm("cvt.rna.tf32.f32 %0, %1;" : "=r"(u) : "f"(x));
    return __uint_as_float(u);
}

__device__ __forceinline__ void mma_tf32(float c[4],
                                         float a0, float a1, float a2, float a3,
                                         float b0, float b1) {
    asm volatile(
        "mma.sync.aligned.m16n8k8.row.col.f32.tf32.tf32.f32 "
        "{%0,%1,%2,%3}, {%4,%5,%6,%7}, {%8,%9}, {%0,%1,%2,%3};"
        : "+f"(c[0]), "+f"(c[1]), "+f"(c[2]), "+f"(c[3])
        : "r"(__float_as_uint(a0)), "r"(__float_as_uint(a1)),
          "r"(__float_as_uint(a2)), "r"(__float_as_uint(a3)),
          "r"(__float_as_uint(b0)), "r"(__float_as_uint(b1)));
}

__global__ __launch_bounds__(NT)
void SimpleRingAttention_76312978915795_kernel(
    const float* __restrict__ q, const float* __restrict__ k,
    const float* __restrict__ v, float* __restrict__ out)
{
    extern __shared__ float sm[];
    float* Qs  = sm;                       // [BM][QP]  tf32, pre-scaled
    float* Kt  = Qs + QS_FLOATS;           // [Dd][KP]  K transposed, tf32
    float* Vs  = Kt + KT_FLOATS;           // [BN][VP]  V row-major, tf32
    float* Ps  = Vs + VS_FLOATS;           // per-warp [16][PP]

    const int tid  = threadIdx.x;
    const int wid  = tid >> 5;
    const int lane = tid & 31;
    const int qr   = lane >> 2;   // 0..7  (row group within quad structure)
    const int ql   = lane & 3;    // 0..3

    const int m0 = blockIdx.x * BM;
    const int h  = blockIdx.y;
    const int b  = blockIdx.z;

    const float scale = 0.125f; // 1/sqrt(64)
    const float* qbase = q + ((size_t)b * Sq + m0) * HD + h * Dd;
    const float* kbase = k + ((size_t)b * Sq) * HD + h * Dd;
    const float* vbase = v + ((size_t)b * Sq) * HD + h * Dd;

    // ---- Stage Q [BM][Dd] -> Qs[row][d], scaled + tf32-rounded ----
    #pragma unroll
    for (int i = 0; i < 8; i++) {
        int idx = tid + i * NT;           // 0..2047 float4 slots
        int row = idx >> 4;
        int d4  = (idx & 15) << 2;
        float4 t = *reinterpret_cast<const float4*>(qbase + (size_t)row * HD + d4);
        float4 r;
        r.x = tf32r(t.x * scale); r.y = tf32r(t.y * scale);
        r.z = tf32r(t.z * scale); r.w = tf32r(t.w * scale);
        *reinterpret_cast<float4*>(&Qs[row * QP + d4]) = r;
    }

    // Per-thread fragment base offsets
    float* ps_w   = Ps + wid * (16 * PP);
    const int qsA = (wid * 16 + qr) * QP + ql;     // Q A-frag base
    const int kB  = ql * KP + qr;                  // K/V B-frag base
    const int psA = qr * PP + ql;                  // P A-frag base

    float oacc[8][4];
    float m_i[2], l_i[2];
    #pragma unroll
    for (int nf = 0; nf < 8; nf++)
        #pragma unroll
        for (int c = 0; c < 4; c++) oacc[nf][c] = 0.0f;
    m_i[0] = m_i[1] = -1e30f;
    l_i[0] = l_i[1] = 0.0f;

    for (int n0 = 0; n0 < Sq; n0 += BN) {
        __syncthreads(); // protect Kt/Vs (and first-iter Qs) against prior reads

        // ---- Load K tile -> Kt[d][kv], V tile -> Vs[kv][d], tf32-rounded ----
        #pragma unroll
        for (int i = 0; i < 4; i++) {
            int idx = tid + i * NT;        // 0..1023 float4 slots
            int row = idx >> 4;            // kv row 0..63
            int d4  = (idx & 15) << 2;
            float4 tk = *reinterpret_cast<const float4*>(kbase + (size_t)(n0 + row) * HD + d4);
            Kt[(d4 + 0) * KP + row] = tf32r(tk.x);
            Kt[(d4 + 1) * KP + row] = tf32r(tk.y);
            Kt[(d4 + 2) * KP + row] = tf32r(tk.z);
            Kt[(d4 + 3) * KP + row] = tf32r(tk.w);
            float4 tv = *reinterpret_cast<const float4*>(vbase + (size_t)(n0 + row) * HD + d4);
            float4 rv;
            rv.x = tf32r(tv.x); rv.y = tf32r(tv.y);
            rv.z = tf32r(tv.z); rv.w = tf32r(tv.w);
            *reinterpret_cast<float4*>(&Vs[row * VP + d4]) = rv;
        }
        __syncthreads();

        // ---- GEMM1: S = Q @ K^T  (warp: 16 x 64) ----
        float sacc[8][4];
        #pragma unroll
        for (int nf = 0; nf < 8; nf++)
            #pragma unroll
            for (int c = 0; c < 4; c++) sacc[nf][c] = 0.0f;

        #pragma unroll
        for (int kf = 0; kf < 8; kf++) {
            float a0 = Qs[qsA + kf * 8];
            float a1 = Qs[qsA + kf * 8 + 8 * QP];
            float a2 = Qs[qsA + kf * 8 + 4];
            float a3 = Qs[qsA + kf * 8 + 8 * QP + 4];
            #pragma unroll
            for (int nf = 0; nf < 8; nf++) {
                float b0 = Kt[kB + kf * 8 * KP + nf * 8];
                float b1 = Kt[kB + (kf * 8 + 4) * KP + nf * 8];
                mma_tf32(sacc[nf], a0, a1, a2, a3, b0, b1);
            }
        }

        // ---- Online softmax (fp32) ----
        #pragma unroll
        for (int hh = 0; hh < 2; hh++) {
            float mt = -1e30f;
            #pragma unroll
            for (int nf = 0; nf < 8; nf++) {
                mt = fmaxf(mt, sacc[nf][2 * hh]);
                mt = fmaxf(mt, sacc[nf][2 * hh + 1]);
            }
            mt = fmaxf(mt, __shfl_xor_sync(0xffffffffu, mt, 1));
            mt = fmaxf(mt, __shfl_xor_sync(0xffffffffu, mt, 2));

            float mnew = fmaxf(m_i[hh], mt);
            float corr = __expf(m_i[hh] - mnew);
            m_i[hh] = mnew;

            float sum = 0.0f;
            #pragma unroll
            for (int nf = 0; nf < 8; nf++) {
                float p0 = __expf(sacc[nf][2 * hh]     - mnew);
                float p1 = __expf(sacc[nf][2 * hh + 1] - mnew);
                sacc[nf][2 * hh]     = p0;
                sacc[nf][2 * hh + 1] = p1;
                sum += p0 + p1;
            }
            sum += __shfl_xor_sync(0xffffffffu, sum, 1);
            sum += __shfl_xor_sync(0xffffffffu, sum, 2);

            l_i[hh] = l_i[hh] * corr + sum;
            #pragma unroll
            for (int nf = 0; nf < 8; nf++) {
                oacc[nf][2 * hh]     *= corr;
                oacc[nf][2 * hh + 1] *= corr;
            }
        }

        // ---- Stage P (per-warp, tf32-rounded) ----
        #pragma unroll
        for (int nf = 0; nf < 8; nf++) {
            #pragma unroll
            for (int hh = 0; hh < 2; hh++) {
                float2 pv;
                pv.x = tf32r(sacc[nf][2 * hh]);
                pv.y = tf32r(sacc[nf][2 * hh + 1]);
                *reinterpret_cast<float2*>(
                    &ps_w[(qr + 8 * hh) * PP + nf * 8 + 2 * ql]) = pv;
            }
        }
        __syncwarp();

        // ---- GEMM2: O += P @ V  (warp: 16 x 64) ----
        #pragma unroll
        for (int kf = 0; kf < 8; kf++) {
            float a0 = ps_w[psA + kf * 8];
            float a1 = ps_w[psA + kf * 8 + 8 * PP];
            float a2 = ps_w[psA + kf * 8 + 4];
            float a3 = ps_w[psA + kf * 8 + 8 * PP + 4];
            #pragma unroll
            for (int nf = 0; nf < 8; nf++) {
                float b0 = Vs[kB + kf * 8 * VP + nf * 8];
                float b1 = Vs[kB + (kf * 8 + 4) * VP + nf * 8];
                mma_tf32(oacc[nf], a0, a1, a2, a3, b0, b1);
            }
        }
        __syncwarp(); // Ps reads done before next tile overwrites (same warp, ordering)
    }

    // ---- Epilogue: normalize, store fp32 ----
    float inv0 = 1.0f / l_i[0];
    float inv1 = 1.0f / l_i[1];
    const int grow0 = m0 + wid * 16 + qr;
    float* obase = out + ((size_t)b * Sq) * HD + h * Dd;
    #pragma unroll
    for (int nf = 0; nf < 8; nf++) {
        int col = nf * 8 + 2 * ql;
        float2 o0, o1;
        o0.x = oacc[nf][0] * inv0; o0.y = oacc[nf][1] * inv0;
        o1.x = oacc[nf][2] * inv1; o1.y = oacc[nf][3] * inv1;
        *reinterpret_cast<float2*>(obase + (size_t)(grow0)     * HD + col) = o0;
        *reinterpret_cast<float2*>(obase + (size_t)(grow0 + 8) * HD + col) = o1;
    }
}

extern "C" void kernel_launch(void* const* d_in, const int* in_sizes, int n_in,
                              void* d_out, int out_size)
{
    (void)in_sizes; (void)n_in; (void)out_size;
    const float* q = (const float*)d_in[0];
    const float* k = (const float*)d_in[1];
    const float* v = (const float*)d_in[2];
    float* out = (float*)d_out;

    cudaFuncSetAttribute(SimpleRingAttention_76312978915795_kernel,
                         cudaFuncAttributeMaxDynamicSharedMemorySize, SMEM_BYTES);

    dim3 grid(Sq / BM, Hh, Bz); // 32 x 8 x 2 = 512 CTAs
    SimpleRingAttention_76312978915795_kernel<<<grid, NT, SMEM_BYTES>>>(q, k, v, out);
}